// round 2
// baseline (speedup 1.0000x reference)
#include <cuda_runtime.h>

#define NN  50000
#define EIN 800000
#define ET  850000   // EIN + NN self loops
#define FIN 256
#define C1  64       // H1*D1
#define C2  128      // H2*C
#define NH  8
#define NEG_SLOPE 0.2f

// ---------------- scratch (device globals; no allocation allowed) ----------
__device__ __align__(16) float g_xw1[NN * C1];
__device__ __align__(16) float g_al1s[NN * NH];
__device__ __align__(16) float g_al1d[NN * NH];
__device__ __align__(16) float g_h1[NN * C1];
__device__ __align__(16) float g_xw2[NN * C2];
__device__ __align__(16) float g_al2s[NN * NH];
__device__ __align__(16) float g_al2d[NN * NH];
__device__ int   g_deg[NN];
__device__ int   g_off[NN + 1];
__device__ int   g_cur[NN];
__device__ int   g_srcs[ET];
__device__ int   g_eid[ET];

// ---------------- CSR build ------------------------------------------------
__global__ void init_deg_k() {
    int n = blockIdx.x * blockDim.x + threadIdx.x;
    if (n < NN) g_deg[n] = 1;   // self loop
}

__global__ void deg_k(const int* __restrict__ ei) {
    int e = blockIdx.x * blockDim.x + threadIdx.x;
    if (e < EIN) {
        int dst = ei[EIN + e];
        atomicAdd(&g_deg[dst], 1);
    }
}

// single-block exclusive scan over 50000 degrees
__global__ void scan_k() {
    __shared__ int part[1024];
    const int CH = (NN + 1023) / 1024;  // 49
    int t = threadIdx.x;
    int start = t * CH;
    int end = start + CH; if (end > NN) end = NN;
    int s = 0;
    for (int i = start; i < end; i++) s += g_deg[i];
    part[t] = s;
    __syncthreads();
    for (int off = 1; off < 1024; off <<= 1) {
        int v = 0;
        if (t >= off) v = part[t - off];
        __syncthreads();
        part[t] += v;
        __syncthreads();
    }
    int run = part[t] - s;  // exclusive prefix
    for (int i = start; i < end; i++) {
        g_off[i] = run;
        g_cur[i] = run;
        run += g_deg[i];
    }
    if (end >= NN && start <= NN) g_off[NN] = run;
}

__global__ void scatter_k(const int* __restrict__ ei) {
    int e = blockIdx.x * blockDim.x + threadIdx.x;
    if (e >= ET) return;
    int src, dst;
    if (e < EIN) { src = ei[e]; dst = ei[EIN + e]; }
    else         { src = e - EIN; dst = src; }
    int pos = atomicAdd(&g_cur[dst], 1);
    g_srcs[pos] = src;
    g_eid[pos] = e;
}

// ---------------- GEMM1: xw1 = x @ W1  (50000x256 @ 256x64) ----------------
__global__ void gemm1_k(const float* __restrict__ A, const float* __restrict__ B) {
    __shared__ float As[16][68];   // [k][row], padded
    __shared__ float Bs[16][64];   // [k][col]
    int tid = threadIdx.x;
    int tx = tid % 16, ty = tid / 16;   // tx -> 4 cols, ty -> 4 rows
    int row0 = blockIdx.x * 64;
    float acc[4][4];
#pragma unroll
    for (int r = 0; r < 4; r++)
#pragma unroll
        for (int c = 0; c < 4; c++) acc[r][c] = 0.f;

    for (int k0 = 0; k0 < FIN; k0 += 16) {
        int ka = tid % 16, rb = tid / 16;
#pragma unroll
        for (int i = 0; i < 4; i++) {
            int r = rb + 16 * i;
            int gr = row0 + r;
            As[ka][r] = (gr < NN) ? A[gr * FIN + k0 + ka] : 0.f;
        }
        int c = tid % 64, kb = tid / 64;
#pragma unroll
        for (int i = 0; i < 4; i++) {
            int kk = kb + 4 * i;
            Bs[kk][c] = B[(k0 + kk) * C1 + c];
        }
        __syncthreads();
#pragma unroll
        for (int kk = 0; kk < 16; kk++) {
            float a[4], b[4];
#pragma unroll
            for (int i = 0; i < 4; i++) a[i] = As[kk][ty * 4 + i];
#pragma unroll
            for (int i = 0; i < 4; i++) b[i] = Bs[kk][tx * 4 + i];
#pragma unroll
            for (int r = 0; r < 4; r++)
#pragma unroll
                for (int cc = 0; cc < 4; cc++) acc[r][cc] += a[r] * b[cc];
        }
        __syncthreads();
    }
#pragma unroll
    for (int r = 0; r < 4; r++) {
        int gr = row0 + ty * 4 + r;
        if (gr < NN) {
#pragma unroll
            for (int cc = 0; cc < 4; cc++)
                g_xw1[gr * C1 + tx * 4 + cc] = acc[r][cc];
        }
    }
}

// ---------------- GEMM2: xw2 = h1 @ W2  (50000x64 @ 64x128) ----------------
__global__ void gemm2_k(const float* __restrict__ B) {
    __shared__ float As[16][68];
    __shared__ float Bs[16][128];
    int tid = threadIdx.x;
    int tx = tid % 16, ty = tid / 16;   // tx -> 8 cols, ty -> 4 rows
    int row0 = blockIdx.x * 64;
    float acc[4][8];
#pragma unroll
    for (int r = 0; r < 4; r++)
#pragma unroll
        for (int c = 0; c < 8; c++) acc[r][c] = 0.f;

    for (int k0 = 0; k0 < C1; k0 += 16) {
        int ka = tid % 16, rb = tid / 16;
#pragma unroll
        for (int i = 0; i < 4; i++) {
            int r = rb + 16 * i;
            int gr = row0 + r;
            As[ka][r] = (gr < NN) ? g_h1[gr * C1 + k0 + ka] : 0.f;
        }
        int c = tid % 128, kb = tid / 128;
#pragma unroll
        for (int i = 0; i < 8; i++) {
            int kk = kb + 2 * i;
            Bs[kk][c] = B[(k0 + kk) * C2 + c];
        }
        __syncthreads();
#pragma unroll
        for (int kk = 0; kk < 16; kk++) {
            float a[4], b[8];
#pragma unroll
            for (int i = 0; i < 4; i++) a[i] = As[kk][ty * 4 + i];
#pragma unroll
            for (int i = 0; i < 8; i++) b[i] = Bs[kk][tx * 8 + i];
#pragma unroll
            for (int r = 0; r < 4; r++)
#pragma unroll
                for (int cc = 0; cc < 8; cc++) acc[r][cc] += a[r] * b[cc];
        }
        __syncthreads();
    }
#pragma unroll
    for (int r = 0; r < 4; r++) {
        int gr = row0 + ty * 4 + r;
        if (gr < NN) {
#pragma unroll
            for (int cc = 0; cc < 8; cc++)
                g_xw2[gr * C2 + tx * 8 + cc] = acc[r][cc];
        }
    }
}

// ---------------- attention-logit dots ------------------------------------
__global__ void al1_k(const float* __restrict__ as, const float* __restrict__ ad) {
    int idx = blockIdx.x * blockDim.x + threadIdx.x;   // n*8 + h
    if (idx >= NN * NH) return;
    int n = idx >> 3, h = idx & 7;
    const float* row = &g_xw1[n * C1 + h * 8];
    float s = 0.f, d = 0.f;
#pragma unroll
    for (int o = 0; o < 8; o++) {
        float v = row[o];
        s += v * as[h * 8 + o];
        d += v * ad[h * 8 + o];
    }
    g_al1s[idx] = s;
    g_al1d[idx] = d;
}

__global__ void al2_k(const float* __restrict__ as, const float* __restrict__ ad) {
    int idx = blockIdx.x * blockDim.x + threadIdx.x;
    if (idx >= NN * NH) return;
    int n = idx >> 3, h = idx & 7;
    const float* row = &g_xw2[n * C2 + h * 16];
    float s = 0.f, d = 0.f;
#pragma unroll
    for (int o = 0; o < 16; o++) {
        float v = row[o];
        s += v * as[h * 16 + o];
        d += v * ad[h * 16 + o];
    }
    g_al2s[idx] = s;
    g_al2d[idx] = d;
}

// ---------------- GAT layer 1: one warp per dst node -----------------------
__global__ void gat1_k(float* __restrict__ alpha_out, const float* __restrict__ b1,
                       int alpha_rows) {
    int lane = threadIdx.x & 31;
    int n = blockIdx.x * (blockDim.x >> 5) + (threadIdx.x >> 5);
    if (n >= NN) return;
    int h = lane >> 2, j = lane & 3;
    int base = g_off[n];
    int deg = g_off[n + 1] - base;
    float ald = g_al1d[n * NH + h];

    // pass 1: max
    float m = -1e30f;
    for (int i = j; i < deg; i += 4) {
        int s = g_srcs[base + i];
        float e = g_al1s[s * NH + h] + ald;
        e = e > 0.f ? e : NEG_SLOPE * e;
        m = fmaxf(m, e);
    }
    m = fmaxf(m, __shfl_xor_sync(0xffffffffu, m, 1));
    m = fmaxf(m, __shfl_xor_sync(0xffffffffu, m, 2));

    // pass 2: sum of exp
    float sum = 0.f;
    for (int i = j; i < deg; i += 4) {
        int s = g_srcs[base + i];
        float e = g_al1s[s * NH + h] + ald;
        e = e > 0.f ? e : NEG_SLOPE * e;
        sum += expf(e - m);
    }
    sum += __shfl_xor_sync(0xffffffffu, sum, 1);
    sum += __shfl_xor_sync(0xffffffffu, sum, 2);
    float inv = 1.f / (sum + 1e-16f);

    // pass 3: alpha + message accumulation
    float acc[8];
#pragma unroll
    for (int o = 0; o < 8; o++) acc[o] = 0.f;
    for (int i = j; i < deg; i += 4) {
        int s = g_srcs[base + i];
        float e = g_al1s[s * NH + h] + ald;
        e = e > 0.f ? e : NEG_SLOPE * e;
        float w = expf(e - m) * inv;
        int eid = g_eid[base + i];
        if (eid < alpha_rows)
            alpha_out[eid * NH + h] = w;
        const float4* xr = (const float4*)&g_xw1[s * C1 + h * 8];
        float4 v0 = xr[0], v1 = xr[1];
        acc[0] += w * v0.x; acc[1] += w * v0.y; acc[2] += w * v0.z; acc[3] += w * v0.w;
        acc[4] += w * v1.x; acc[5] += w * v1.y; acc[6] += w * v1.z; acc[7] += w * v1.w;
    }
#pragma unroll
    for (int o = 0; o < 8; o++) {
        acc[o] += __shfl_xor_sync(0xffffffffu, acc[o], 1);
        acc[o] += __shfl_xor_sync(0xffffffffu, acc[o], 2);
    }
    if (j == 0) {
        float r[8];
#pragma unroll
        for (int o = 0; o < 8; o++) {
            float v = acc[o] + b1[h * 8 + o];
            r[o] = v > 0.f ? v : expm1f(v);   // ELU
        }
        float4* dst = (float4*)&g_h1[n * C1 + h * 8];
        dst[0] = make_float4(r[0], r[1], r[2], r[3]);
        dst[1] = make_float4(r[4], r[5], r[6], r[7]);
    }
}

// ---------------- GAT layer 2 + log_softmax --------------------------------
__global__ void gat2_k(float* __restrict__ logp, const float* __restrict__ b2) {
    __shared__ float buf[8][C2];
    int lane = threadIdx.x & 31;
    int w = threadIdx.x >> 5;
    int n = blockIdx.x * (blockDim.x >> 5) + w;
    if (n >= NN) return;
    int h = lane >> 2, j = lane & 3;
    int base = g_off[n];
    int deg = g_off[n + 1] - base;
    float ald = g_al2d[n * NH + h];

    float m = -1e30f;
    for (int i = j; i < deg; i += 4) {
        int s = g_srcs[base + i];
        float e = g_al2s[s * NH + h] + ald;
        e = e > 0.f ? e : NEG_SLOPE * e;
        m = fmaxf(m, e);
    }
    m = fmaxf(m, __shfl_xor_sync(0xffffffffu, m, 1));
    m = fmaxf(m, __shfl_xor_sync(0xffffffffu, m, 2));

    float sum = 0.f;
    for (int i = j; i < deg; i += 4) {
        int s = g_srcs[base + i];
        float e = g_al2s[s * NH + h] + ald;
        e = e > 0.f ? e : NEG_SLOPE * e;
        sum += expf(e - m);
    }
    sum += __shfl_xor_sync(0xffffffffu, sum, 1);
    sum += __shfl_xor_sync(0xffffffffu, sum, 2);
    float inv = 1.f / (sum + 1e-16f);

    float acc[16];
#pragma unroll
    for (int o = 0; o < 16; o++) acc[o] = 0.f;
    for (int i = j; i < deg; i += 4) {
        int s = g_srcs[base + i];
        float e = g_al2s[s * NH + h] + ald;
        e = e > 0.f ? e : NEG_SLOPE * e;
        float wgt = expf(e - m) * inv;
        const float4* xr = (const float4*)&g_xw2[s * C2 + h * 16];
#pragma unroll
        for (int q = 0; q < 4; q++) {
            float4 v = xr[q];
            acc[q * 4 + 0] += wgt * v.x;
            acc[q * 4 + 1] += wgt * v.y;
            acc[q * 4 + 2] += wgt * v.z;
            acc[q * 4 + 3] += wgt * v.w;
        }
    }
#pragma unroll
    for (int o = 0; o < 16; o++) {
        acc[o] += __shfl_xor_sync(0xffffffffu, acc[o], 1);
        acc[o] += __shfl_xor_sync(0xffffffffu, acc[o], 2);
    }
    if (j == 0) {
#pragma unroll
        for (int o = 0; o < 16; o++)
            buf[w][h * 16 + o] = acc[o] + b2[h * 16 + o];
    }
    __syncwarp();

    // log_softmax over the 128 logits of this node
    float v[4];
#pragma unroll
    for (int i = 0; i < 4; i++) v[i] = buf[w][lane * 4 + i];
    float mx = fmaxf(fmaxf(v[0], v[1]), fmaxf(v[2], v[3]));
#pragma unroll
    for (int off = 16; off >= 1; off >>= 1)
        mx = fmaxf(mx, __shfl_xor_sync(0xffffffffu, mx, off));
    float se = 0.f;
#pragma unroll
    for (int i = 0; i < 4; i++) se += expf(v[i] - mx);
#pragma unroll
    for (int off = 16; off >= 1; off >>= 1)
        se += __shfl_xor_sync(0xffffffffu, se, off);
    float lse = mx + logf(se);
    float4 o4 = make_float4(v[0] - lse, v[1] - lse, v[2] - lse, v[3] - lse);
    *(float4*)&logp[n * C2 + lane * 4] = o4;
}

// ---------------- launch ---------------------------------------------------
extern "C" void kernel_launch(void* const* d_in, const int* in_sizes, int n_in,
                              void* d_out, int out_size) {
    const float* x   = (const float*)d_in[0];
    const int*   ei  = (const int*)d_in[1];   // int32: JAX default (x64 disabled)
    const float* W1  = (const float*)d_in[2];
    const float* a1s = (const float*)d_in[3];
    const float* a1d = (const float*)d_in[4];
    const float* b1  = (const float*)d_in[5];
    const float* W2  = (const float*)d_in[6];
    const float* a2s = (const float*)d_in[7];
    const float* a2d = (const float*)d_in[8];
    const float* b2  = (const float*)d_in[9];

    float* out   = (float*)d_out;
    float* logp  = out;                // [NN, 128]
    float* alpha = out + NN * C2;      // [ET, 8]
    int alpha_rows = (out_size - NN * C2) / NH;
    if (alpha_rows < 0) alpha_rows = 0;

    init_deg_k<<<(NN + 255) / 256, 256>>>();
    deg_k<<<(EIN + 255) / 256, 256>>>(ei);
    scan_k<<<1, 1024>>>();
    scatter_k<<<(ET + 255) / 256, 256>>>(ei);

    gemm1_k<<<(NN + 63) / 64, 256>>>(x, W1);
    al1_k<<<(NN * NH + 255) / 256, 256>>>(a1s, a1d);
    gat1_k<<<(NN + 7) / 8, 256>>>(alpha, b1, alpha_rows);

    gemm2_k<<<(NN + 63) / 64, 256>>>(W2);
    al2_k<<<(NN * NH + 255) / 256, 256>>>(a2s, a2d);
    gat2_k<<<(NN + 7) / 8, 256>>>(logp, b2);
}

// round 3
// speedup vs baseline: 1.0482x; 1.0482x over previous
#include <cuda_runtime.h>

#define NN  50000
#define EIN 800000
#define ET  850000   // EIN + NN self loops
#define FIN 256
#define C1  64       // H1*D1
#define C2  128      // H2*C
#define NH  8
#define NEG_SLOPE 0.2f

// ---------------- scratch (device globals; no allocation allowed) ----------
__device__ __align__(16) float g_xw1[NN * C1];
__device__ __align__(16) float g_al1s[NN * NH];
__device__ __align__(16) float g_al1d[NN * NH];
__device__ __align__(16) float g_h1[NN * C1];
__device__ __align__(16) float g_xw2[NN * C2];
__device__ __align__(16) float g_al2s[NN * NH];
__device__ __align__(16) float g_al2d[NN * NH];
__device__ int   g_deg[NN];
__device__ int   g_off[NN + 1];
__device__ int   g_cur[NN];
__device__ int   g_srcs[ET];
__device__ int   g_eid[ET];

// ---------------- CSR build ------------------------------------------------
__global__ void init_deg_k() {
    int n = blockIdx.x * blockDim.x + threadIdx.x;
    if (n < NN) g_deg[n] = 1;   // self loop
}

__global__ void deg_k(const int* __restrict__ ei) {
    int e = blockIdx.x * blockDim.x + threadIdx.x;
    if (e < EIN) {
        int dst = ei[EIN + e];
        atomicAdd(&g_deg[dst], 1);
    }
}

// single-block exclusive scan over 50000 degrees
__global__ void scan_k() {
    __shared__ int part[1024];
    const int CH = (NN + 1023) / 1024;  // 49
    int t = threadIdx.x;
    int start = t * CH;
    int end = start + CH; if (end > NN) end = NN;
    if (start > NN) start = NN;
    int s = 0;
    for (int i = start; i < end; i++) s += g_deg[i];
    part[t] = s;
    __syncthreads();
    for (int off = 1; off < 1024; off <<= 1) {
        int v = 0;
        if (t >= off) v = part[t - off];
        __syncthreads();
        part[t] += v;
        __syncthreads();
    }
    int run = part[t] - s;  // exclusive prefix
    for (int i = start; i < end; i++) {
        g_off[i] = run;
        g_cur[i] = run;
        run += g_deg[i];
    }
    if (end >= NN && start <= NN) g_off[NN] = run;
}

__global__ void scatter_k(const int* __restrict__ ei) {
    int e = blockIdx.x * blockDim.x + threadIdx.x;
    if (e >= ET) return;
    int src, dst;
    if (e < EIN) { src = ei[e]; dst = ei[EIN + e]; }
    else         { src = e - EIN; dst = src; }
    int pos = atomicAdd(&g_cur[dst], 1);
    g_srcs[pos] = src;
    g_eid[pos] = e;
}

// ---------------- GEMM1: xw1 = x @ W1  (50000x256 @ 256x64) ----------------
__global__ void gemm1_k(const float* __restrict__ A, const float* __restrict__ B) {
    __shared__ float As[16][68];   // [k][row], padded
    __shared__ float Bs[16][64];   // [k][col]
    int tid = threadIdx.x;
    int tx = tid % 16, ty = tid / 16;   // tx -> 4 cols, ty -> 4 rows
    int row0 = blockIdx.x * 64;
    float acc[4][4];
#pragma unroll
    for (int r = 0; r < 4; r++)
#pragma unroll
        for (int c = 0; c < 4; c++) acc[r][c] = 0.f;

    for (int k0 = 0; k0 < FIN; k0 += 16) {
        int ka = tid % 16, rb = tid / 16;
#pragma unroll
        for (int i = 0; i < 4; i++) {
            int r = rb + 16 * i;
            int gr = row0 + r;
            As[ka][r] = (gr < NN) ? A[gr * FIN + k0 + ka] : 0.f;
        }
        int c = tid % 64, kb = tid / 64;
#pragma unroll
        for (int i = 0; i < 4; i++) {
            int kk = kb + 4 * i;
            Bs[kk][c] = B[(k0 + kk) * C1 + c];
        }
        __syncthreads();
#pragma unroll
        for (int kk = 0; kk < 16; kk++) {
            float a[4], b[4];
            *(float4*)a = *(const float4*)&As[kk][ty * 4];
            *(float4*)b = *(const float4*)&Bs[kk][tx * 4];
#pragma unroll
            for (int r = 0; r < 4; r++)
#pragma unroll
                for (int cc = 0; cc < 4; cc++) acc[r][cc] += a[r] * b[cc];
        }
        __syncthreads();
    }
#pragma unroll
    for (int r = 0; r < 4; r++) {
        int gr = row0 + ty * 4 + r;
        if (gr < NN) {
            *(float4*)&g_xw1[gr * C1 + tx * 4] = *(float4*)acc[r];
        }
    }
}

// ---------------- GEMM2: xw2 = h1 @ W2  (50000x64 @ 64x128) ----------------
__global__ void gemm2_k(const float* __restrict__ B) {
    __shared__ float As[16][68];
    __shared__ float Bs[16][128];
    int tid = threadIdx.x;
    int tx = tid % 16, ty = tid / 16;   // tx -> 8 cols, ty -> 4 rows
    int row0 = blockIdx.x * 64;
    float acc[4][8];
#pragma unroll
    for (int r = 0; r < 4; r++)
#pragma unroll
        for (int c = 0; c < 8; c++) acc[r][c] = 0.f;

    for (int k0 = 0; k0 < C1; k0 += 16) {
        int ka = tid % 16, rb = tid / 16;
#pragma unroll
        for (int i = 0; i < 4; i++) {
            int r = rb + 16 * i;
            int gr = row0 + r;
            As[ka][r] = (gr < NN) ? g_h1[gr * C1 + k0 + ka] : 0.f;
        }
        int c = tid % 128, kb = tid / 128;
#pragma unroll
        for (int i = 0; i < 8; i++) {
            int kk = kb + 2 * i;
            Bs[kk][c] = B[(k0 + kk) * C2 + c];
        }
        __syncthreads();
#pragma unroll
        for (int kk = 0; kk < 16; kk++) {
            float a[4], b[8];
            *(float4*)a = *(const float4*)&As[kk][ty * 4];
            *(float4*)&b[0] = *(const float4*)&Bs[kk][tx * 8];
            *(float4*)&b[4] = *(const float4*)&Bs[kk][tx * 8 + 4];
#pragma unroll
            for (int r = 0; r < 4; r++)
#pragma unroll
                for (int cc = 0; cc < 8; cc++) acc[r][cc] += a[r] * b[cc];
        }
        __syncthreads();
    }
#pragma unroll
    for (int r = 0; r < 4; r++) {
        int gr = row0 + ty * 4 + r;
        if (gr < NN) {
            *(float4*)&g_xw2[gr * C2 + tx * 8]     = *(float4*)&acc[r][0];
            *(float4*)&g_xw2[gr * C2 + tx * 8 + 4] = *(float4*)&acc[r][4];
        }
    }
}

// ---------------- attention-logit dots ------------------------------------
__global__ void al1_k(const float* __restrict__ as, const float* __restrict__ ad) {
    int idx = blockIdx.x * blockDim.x + threadIdx.x;   // n*8 + h
    if (idx >= NN * NH) return;
    int n = idx >> 3, h = idx & 7;
    const float4* row = (const float4*)&g_xw1[n * C1 + h * 8];
    const float4* av = (const float4*)&as[h * 8];
    const float4* dv = (const float4*)&ad[h * 8];
    float s = 0.f, d = 0.f;
#pragma unroll
    for (int q = 0; q < 2; q++) {
        float4 v = row[q], a4 = av[q], d4 = dv[q];
        s += v.x * a4.x + v.y * a4.y + v.z * a4.z + v.w * a4.w;
        d += v.x * d4.x + v.y * d4.y + v.z * d4.z + v.w * d4.w;
    }
    g_al1s[idx] = s;
    g_al1d[idx] = d;
}

__global__ void al2_k(const float* __restrict__ as, const float* __restrict__ ad) {
    int idx = blockIdx.x * blockDim.x + threadIdx.x;
    if (idx >= NN * NH) return;
    int n = idx >> 3, h = idx & 7;
    const float4* row = (const float4*)&g_xw2[n * C2 + h * 16];
    const float4* av = (const float4*)&as[h * 16];
    const float4* dv = (const float4*)&ad[h * 16];
    float s = 0.f, d = 0.f;
#pragma unroll
    for (int q = 0; q < 4; q++) {
        float4 v = row[q], a4 = av[q], d4 = dv[q];
        s += v.x * a4.x + v.y * a4.y + v.z * a4.z + v.w * a4.w;
        d += v.x * d4.x + v.y * d4.y + v.z * d4.z + v.w * d4.w;
    }
    g_al2s[idx] = s;
    g_al2d[idx] = d;
}

// ---------------- GAT layer 1: one warp per dst node, 2 passes -------------
__global__ void gat1_k(float* __restrict__ alpha_out, const float* __restrict__ b1,
                       int alpha_rows) {
    int lane = threadIdx.x & 31;
    int n = blockIdx.x * (blockDim.x >> 5) + (threadIdx.x >> 5);
    if (n >= NN) return;
    int h = lane >> 2, j = lane & 3;
    int base = g_off[n];
    int deg = g_off[n + 1] - base;
    float ald = g_al1d[n * NH + h];

    // pass 1: online max + sum-exp
    float m = -1e30f, s = 0.f;
    for (int i = j; i < deg; i += 4) {
        int sr = g_srcs[base + i];
        float e = g_al1s[sr * NH + h] + ald;
        e = e > 0.f ? e : NEG_SLOPE * e;
        if (e > m) {
            s *= __expf(m - e);
            m = e;
        }
        s += __expf(e - m);
    }
    // combine m,s across the 4 j-lanes (butterfly; all lanes end with result)
#pragma unroll
    for (int mask = 1; mask <= 2; mask <<= 1) {
        float mo = __shfl_xor_sync(0xffffffffu, m, mask);
        float so = __shfl_xor_sync(0xffffffffu, s, mask);
        float mm = fmaxf(m, mo);
        s = s * __expf(m - mm) + so * __expf(mo - mm);
        m = mm;
    }
    float inv = 1.f / (s + 1e-16f);

    // pass 2: alpha + message accumulation
    float acc[8];
#pragma unroll
    for (int o = 0; o < 8; o++) acc[o] = 0.f;
    for (int i = j; i < deg; i += 4) {
        int sr = g_srcs[base + i];
        float e = g_al1s[sr * NH + h] + ald;
        e = e > 0.f ? e : NEG_SLOPE * e;
        float w = __expf(e - m) * inv;
        int eid = g_eid[base + i];
        if (eid < alpha_rows)
            alpha_out[eid * NH + h] = w;
        const float4* xr = (const float4*)&g_xw1[sr * C1 + h * 8];
        float4 v0 = xr[0], v1 = xr[1];
        acc[0] += w * v0.x; acc[1] += w * v0.y; acc[2] += w * v0.z; acc[3] += w * v0.w;
        acc[4] += w * v1.x; acc[5] += w * v1.y; acc[6] += w * v1.z; acc[7] += w * v1.w;
    }
#pragma unroll
    for (int o = 0; o < 8; o++) {
        acc[o] += __shfl_xor_sync(0xffffffffu, acc[o], 1);
        acc[o] += __shfl_xor_sync(0xffffffffu, acc[o], 2);
    }
    if (j == 0) {
        float r[8];
#pragma unroll
        for (int o = 0; o < 8; o++) {
            float v = acc[o] + b1[h * 8 + o];
            r[o] = v > 0.f ? v : (__expf(v) - 1.f);   // ELU
        }
        float4* dst = (float4*)&g_h1[n * C1 + h * 8];
        dst[0] = make_float4(r[0], r[1], r[2], r[3]);
        dst[1] = make_float4(r[4], r[5], r[6], r[7]);
    }
}

// ---------------- GAT layer 2 + log_softmax: single online pass ------------
__global__ void gat2_k(float* __restrict__ logp, const float* __restrict__ b2) {
    __shared__ float buf[8][C2];
    int lane = threadIdx.x & 31;
    int w = threadIdx.x >> 5;
    int n = blockIdx.x * (blockDim.x >> 5) + w;
    if (n >= NN) return;
    int h = lane >> 2, j = lane & 3;
    int base = g_off[n];
    int deg = g_off[n + 1] - base;
    float ald = g_al2d[n * NH + h];

    float m = -1e30f, s = 0.f;
    float acc[16];
#pragma unroll
    for (int o = 0; o < 16; o++) acc[o] = 0.f;

    for (int i = j; i < deg; i += 4) {
        int sr = g_srcs[base + i];
        float e = g_al2s[sr * NH + h] + ald;
        e = e > 0.f ? e : NEG_SLOPE * e;
        if (e > m) {
            float r = __expf(m - e);
            s *= r;
#pragma unroll
            for (int o = 0; o < 16; o++) acc[o] *= r;
            m = e;
        }
        float wgt = __expf(e - m);
        s += wgt;
        const float4* xr = (const float4*)&g_xw2[sr * C2 + h * 16];
#pragma unroll
        for (int q = 0; q < 4; q++) {
            float4 v = xr[q];
            acc[q * 4 + 0] += wgt * v.x;
            acc[q * 4 + 1] += wgt * v.y;
            acc[q * 4 + 2] += wgt * v.z;
            acc[q * 4 + 3] += wgt * v.w;
        }
    }
    // butterfly combine (m, s, acc) across the 4 j-lanes
#pragma unroll
    for (int mask = 1; mask <= 2; mask <<= 1) {
        float mo = __shfl_xor_sync(0xffffffffu, m, mask);
        float so = __shfl_xor_sync(0xffffffffu, s, mask);
        float mm = fmaxf(m, mo);
        float cs = __expf(m - mm), co = __expf(mo - mm);
        s = s * cs + so * co;
#pragma unroll
        for (int o = 0; o < 16; o++) {
            float ao = __shfl_xor_sync(0xffffffffu, acc[o], mask);
            acc[o] = acc[o] * cs + ao * co;
        }
        m = mm;
    }
    if (j == 0) {
        float inv = 1.f / (s + 1e-16f);
#pragma unroll
        for (int o = 0; o < 16; o++)
            buf[w][h * 16 + o] = acc[o] * inv + b2[h * 16 + o];
    }
    __syncwarp();

    // log_softmax over the 128 logits of this node
    float v[4];
#pragma unroll
    for (int i = 0; i < 4; i++) v[i] = buf[w][lane * 4 + i];
    float mx = fmaxf(fmaxf(v[0], v[1]), fmaxf(v[2], v[3]));
#pragma unroll
    for (int off = 16; off >= 1; off >>= 1)
        mx = fmaxf(mx, __shfl_xor_sync(0xffffffffu, mx, off));
    float se = 0.f;
#pragma unroll
    for (int i = 0; i < 4; i++) se += __expf(v[i] - mx);
#pragma unroll
    for (int off = 16; off >= 1; off >>= 1)
        se += __shfl_xor_sync(0xffffffffu, se, off);
    float lse = mx + __logf(se);
    float4 o4 = make_float4(v[0] - lse, v[1] - lse, v[2] - lse, v[3] - lse);
    *(float4*)&logp[n * C2 + lane * 4] = o4;
}

// ---------------- launch ---------------------------------------------------
extern "C" void kernel_launch(void* const* d_in, const int* in_sizes, int n_in,
                              void* d_out, int out_size) {
    const float* x   = (const float*)d_in[0];
    const int*   ei  = (const int*)d_in[1];   // int32: JAX default (x64 disabled)
    const float* W1  = (const float*)d_in[2];
    const float* a1s = (const float*)d_in[3];
    const float* a1d = (const float*)d_in[4];
    const float* b1  = (const float*)d_in[5];
    const float* W2  = (const float*)d_in[6];
    const float* a2s = (const float*)d_in[7];
    const float* a2d = (const float*)d_in[8];
    const float* b2  = (const float*)d_in[9];

    float* out   = (float*)d_out;
    float* logp  = out;                // [NN, 128]
    float* alpha = out + NN * C2;      // [ET, 8]
    int alpha_rows = (out_size - NN * C2) / NH;
    if (alpha_rows < 0) alpha_rows = 0;

    init_deg_k<<<(NN + 255) / 256, 256>>>();
    deg_k<<<(EIN + 255) / 256, 256>>>(ei);
    scan_k<<<1, 1024>>>();
    scatter_k<<<(ET + 255) / 256, 256>>>(ei);

    gemm1_k<<<(NN + 63) / 64, 256>>>(x, W1);
    al1_k<<<(NN * NH + 255) / 256, 256>>>(a1s, a1d);
    gat1_k<<<(NN + 7) / 8, 256>>>(alpha, b1, alpha_rows);

    gemm2_k<<<(NN + 63) / 64, 256>>>(W2);
    al2_k<<<(NN * NH + 255) / 256, 256>>>(a2s, a2d);
    gat2_k<<<(NN + 7) / 8, 256>>>(logp, b2);
}

// round 4
// speedup vs baseline: 1.2905x; 1.2311x over previous
#include <cuda_runtime.h>

#define NN  50000
#define EIN 800000
#define ET  850000   // EIN + NN self loops
#define FIN 256
#define C1  64       // H1*D1
#define C2  128      // H2*C
#define NH  8
#define NEG_SLOPE 0.2f

// ---------------- scratch (device globals; no allocation allowed) ----------
__device__ __align__(16) float g_xw1[NN * C1];
__device__ __align__(16) float g_al1s[NN * NH];
__device__ __align__(16) float g_al1d[NN * NH];
__device__ __align__(16) float g_h1[NN * C1];
__device__ __align__(16) float g_xw2[NN * C2];
__device__ __align__(16) float g_al2s[NN * NH];
__device__ __align__(16) float g_al2d[NN * NH];
__device__ __align__(16) int   g_deg[NN];
__device__ int   g_off[NN + 1];
__device__ int   g_cur[NN];
__device__ int   g_srcs[ET];
__device__ int   g_eid[ET];

// ---------------- CSR build ------------------------------------------------
__global__ void init_deg_k() {
    int n4 = blockIdx.x * blockDim.x + threadIdx.x;
    if (n4 * 4 + 3 < NN) {
        *(int4*)&g_deg[n4 * 4] = make_int4(1, 1, 1, 1);
    } else {
        for (int n = n4 * 4; n < NN; n++) g_deg[n] = 1;
    }
}

__global__ void deg_k(const int* __restrict__ ei) {
    int e4 = blockIdx.x * blockDim.x + threadIdx.x;
    if (e4 * 4 >= EIN) return;
    int4 d = *(const int4*)&ei[EIN + e4 * 4];   // EIN % 4 == 0
    atomicAdd(&g_deg[d.x], 1);
    atomicAdd(&g_deg[d.y], 1);
    atomicAdd(&g_deg[d.z], 1);
    atomicAdd(&g_deg[d.w], 1);
}

// single-block exclusive scan over 50000 degrees
__global__ void scan_k() {
    __shared__ int part[1024];
    const int CH = (NN + 1023) / 1024;  // 49
    int t = threadIdx.x;
    int start = t * CH;
    int end = start + CH; if (end > NN) end = NN;
    if (start > NN) start = NN;
    int s = 0;
    for (int i = start; i < end; i++) s += g_deg[i];
    part[t] = s;
    __syncthreads();
    for (int off = 1; off < 1024; off <<= 1) {
        int v = 0;
        if (t >= off) v = part[t - off];
        __syncthreads();
        part[t] += v;
        __syncthreads();
    }
    int run = part[t] - s;  // exclusive prefix
    for (int i = start; i < end; i++) {
        g_off[i] = run;
        g_cur[i] = run;
        run += g_deg[i];
    }
    if (end >= NN && start <= NN) g_off[NN] = run;
}

// 4 edges per thread; threads beyond EIN/4 handle self loops (4 per thread)
__global__ void scatter_k(const int* __restrict__ ei) {
    const int NE4 = EIN / 4;              // 200000
    int t = blockIdx.x * blockDim.x + threadIdx.x;
    if (t < NE4) {
        int e = t * 4;
        int4 s = *(const int4*)&ei[e];
        int4 d = *(const int4*)&ei[EIN + e];
        int p;
        p = atomicAdd(&g_cur[d.x], 1); g_srcs[p] = s.x; g_eid[p] = e;
        p = atomicAdd(&g_cur[d.y], 1); g_srcs[p] = s.y; g_eid[p] = e + 1;
        p = atomicAdd(&g_cur[d.z], 1); g_srcs[p] = s.z; g_eid[p] = e + 2;
        p = atomicAdd(&g_cur[d.w], 1); g_srcs[p] = s.w; g_eid[p] = e + 3;
    } else {
        int n0 = (t - NE4) * 4;
        for (int k = 0; k < 4; k++) {
            int n = n0 + k;
            if (n < NN) {
                int p = atomicAdd(&g_cur[n], 1);
                g_srcs[p] = n; g_eid[p] = EIN + n;
            }
        }
    }
}

// ---------------- GEMM1: xw1 = x @ W1  (50000x256 @ 256x64) ----------------
// 128x64 tile, 256 threads, 8x4 per thread
__global__ __launch_bounds__(256, 4) void gemm1_k(const float* __restrict__ A,
                                                  const float* __restrict__ B) {
    __shared__ float As[16][132];   // [k][row], padded
    __shared__ float Bs[16][64];    // [k][col]
    int tid = threadIdx.x;
    int tx = tid % 16, ty = tid / 16;   // tx -> 4 cols, ty -> 8 rows
    int row0 = blockIdx.x * 128;
    float acc[8][4];
#pragma unroll
    for (int r = 0; r < 8; r++)
#pragma unroll
        for (int c = 0; c < 4; c++) acc[r][c] = 0.f;

    for (int k0 = 0; k0 < FIN; k0 += 16) {
        int ka = tid % 16, rb = tid / 16;
#pragma unroll
        for (int i = 0; i < 8; i++) {
            int r = rb + 16 * i;
            int gr = row0 + r;
            As[ka][r] = (gr < NN) ? A[gr * FIN + k0 + ka] : 0.f;
        }
        int c = tid % 64, kb = tid / 64;
#pragma unroll
        for (int i = 0; i < 4; i++) {
            int kk = kb + 4 * i;
            Bs[kk][c] = B[(k0 + kk) * C1 + c];
        }
        __syncthreads();
#pragma unroll
        for (int kk = 0; kk < 16; kk++) {
            float a[8], b[4];
            *(float4*)&a[0] = *(const float4*)&As[kk][ty * 8];
            *(float4*)&a[4] = *(const float4*)&As[kk][ty * 8 + 4];
            *(float4*)b = *(const float4*)&Bs[kk][tx * 4];
#pragma unroll
            for (int r = 0; r < 8; r++)
#pragma unroll
                for (int cc = 0; cc < 4; cc++) acc[r][cc] += a[r] * b[cc];
        }
        __syncthreads();
    }
#pragma unroll
    for (int r = 0; r < 8; r++) {
        int gr = row0 + ty * 8 + r;
        if (gr < NN)
            *(float4*)&g_xw1[gr * C1 + tx * 4] = *(float4*)acc[r];
    }
}

// ---------------- GEMM2: xw2 = h1 @ W2  (50000x64 @ 64x128) ----------------
// 128x128 tile, 256 threads, 8x8 per thread
__global__ __launch_bounds__(256, 2) void gemm2_k(const float* __restrict__ B) {
    __shared__ float As[16][132];
    __shared__ float Bs[16][128];
    int tid = threadIdx.x;
    int tx = tid % 16, ty = tid / 16;   // tx -> 8 cols, ty -> 8 rows
    int row0 = blockIdx.x * 128;
    float acc[8][8];
#pragma unroll
    for (int r = 0; r < 8; r++)
#pragma unroll
        for (int c = 0; c < 8; c++) acc[r][c] = 0.f;

    for (int k0 = 0; k0 < C1; k0 += 16) {
        int ka = tid % 16, rb = tid / 16;
#pragma unroll
        for (int i = 0; i < 8; i++) {
            int r = rb + 16 * i;
            int gr = row0 + r;
            As[ka][r] = (gr < NN) ? g_h1[gr * C1 + k0 + ka] : 0.f;
        }
        int c = tid % 128, kb = tid / 128;
#pragma unroll
        for (int i = 0; i < 8; i++) {
            int kk = kb + 2 * i;
            Bs[kk][c] = B[(k0 + kk) * C2 + c];
        }
        __syncthreads();
#pragma unroll
        for (int kk = 0; kk < 16; kk++) {
            float a[8], b[8];
            *(float4*)&a[0] = *(const float4*)&As[kk][ty * 8];
            *(float4*)&a[4] = *(const float4*)&As[kk][ty * 8 + 4];
            *(float4*)&b[0] = *(const float4*)&Bs[kk][tx * 8];
            *(float4*)&b[4] = *(const float4*)&Bs[kk][tx * 8 + 4];
#pragma unroll
            for (int r = 0; r < 8; r++)
#pragma unroll
                for (int cc = 0; cc < 8; cc++) acc[r][cc] += a[r] * b[cc];
        }
        __syncthreads();
    }
#pragma unroll
    for (int r = 0; r < 8; r++) {
        int gr = row0 + ty * 8 + r;
        if (gr < NN) {
            *(float4*)&g_xw2[gr * C2 + tx * 8]     = *(float4*)&acc[r][0];
            *(float4*)&g_xw2[gr * C2 + tx * 8 + 4] = *(float4*)&acc[r][4];
        }
    }
}

// ---------------- attention-logit dots ------------------------------------
__global__ void al1_k(const float* __restrict__ as, const float* __restrict__ ad) {
    int idx = blockIdx.x * blockDim.x + threadIdx.x;   // n*8 + h
    if (idx >= NN * NH) return;
    int n = idx >> 3, h = idx & 7;
    const float4* row = (const float4*)&g_xw1[n * C1 + h * 8];
    const float4* av = (const float4*)&as[h * 8];
    const float4* dv = (const float4*)&ad[h * 8];
    float s = 0.f, d = 0.f;
#pragma unroll
    for (int q = 0; q < 2; q++) {
        float4 v = row[q], a4 = av[q], d4 = dv[q];
        s += v.x * a4.x + v.y * a4.y + v.z * a4.z + v.w * a4.w;
        d += v.x * d4.x + v.y * d4.y + v.z * d4.z + v.w * d4.w;
    }
    g_al1s[idx] = s;
    g_al1d[idx] = d;
}

__global__ void al2_k(const float* __restrict__ as, const float* __restrict__ ad) {
    int idx = blockIdx.x * blockDim.x + threadIdx.x;
    if (idx >= NN * NH) return;
    int n = idx >> 3, h = idx & 7;
    const float4* row = (const float4*)&g_xw2[n * C2 + h * 16];
    const float4* av = (const float4*)&as[h * 16];
    const float4* dv = (const float4*)&ad[h * 16];
    float s = 0.f, d = 0.f;
#pragma unroll
    for (int q = 0; q < 4; q++) {
        float4 v = row[q], a4 = av[q], d4 = dv[q];
        s += v.x * a4.x + v.y * a4.y + v.z * a4.z + v.w * a4.w;
        d += v.x * d4.x + v.y * d4.y + v.z * d4.z + v.w * d4.w;
    }
    g_al2s[idx] = s;
    g_al2d[idx] = d;
}

// ---------------- GAT layer 1: one warp per dst node, 2 passes -------------
__global__ void gat1_k(float* __restrict__ alpha_out, const float* __restrict__ b1,
                       int alpha_rows) {
    int lane = threadIdx.x & 31;
    int n = blockIdx.x * (blockDim.x >> 5) + (threadIdx.x >> 5);
    if (n >= NN) return;
    int h = lane >> 2, j = lane & 3;
    int base = g_off[n];
    int deg = g_off[n + 1] - base;
    float ald = g_al1d[n * NH + h];

    // pass 1: online max + sum-exp
    float m = -1e30f, s = 0.f;
    for (int i = j; i < deg; i += 4) {
        int sr = g_srcs[base + i];
        float e = g_al1s[sr * NH + h] + ald;
        e = e > 0.f ? e : NEG_SLOPE * e;
        if (e > m) {
            s *= __expf(m - e);
            m = e;
        }
        s += __expf(e - m);
    }
#pragma unroll
    for (int mask = 1; mask <= 2; mask <<= 1) {
        float mo = __shfl_xor_sync(0xffffffffu, m, mask);
        float so = __shfl_xor_sync(0xffffffffu, s, mask);
        float mm = fmaxf(m, mo);
        s = s * __expf(m - mm) + so * __expf(mo - mm);
        m = mm;
    }
    float inv = 1.f / (s + 1e-16f);

    // pass 2: alpha + message accumulation
    float acc[8];
#pragma unroll
    for (int o = 0; o < 8; o++) acc[o] = 0.f;
    for (int i = j; i < deg; i += 4) {
        int sr = g_srcs[base + i];
        float e = g_al1s[sr * NH + h] + ald;
        e = e > 0.f ? e : NEG_SLOPE * e;
        float w = __expf(e - m) * inv;
        int eid = g_eid[base + i];
        if (eid < alpha_rows)
            alpha_out[eid * NH + h] = w;
        const float4* xr = (const float4*)&g_xw1[sr * C1 + h * 8];
        float4 v0 = xr[0], v1 = xr[1];
        acc[0] += w * v0.x; acc[1] += w * v0.y; acc[2] += w * v0.z; acc[3] += w * v0.w;
        acc[4] += w * v1.x; acc[5] += w * v1.y; acc[6] += w * v1.z; acc[7] += w * v1.w;
    }
#pragma unroll
    for (int o = 0; o < 8; o++) {
        acc[o] += __shfl_xor_sync(0xffffffffu, acc[o], 1);
        acc[o] += __shfl_xor_sync(0xffffffffu, acc[o], 2);
    }
    if (j == 0) {
        float r[8];
#pragma unroll
        for (int o = 0; o < 8; o++) {
            float v = acc[o] + b1[h * 8 + o];
            r[o] = v > 0.f ? v : (__expf(v) - 1.f);   // ELU
        }
        float4* dst = (float4*)&g_h1[n * C1 + h * 8];
        dst[0] = make_float4(r[0], r[1], r[2], r[3]);
        dst[1] = make_float4(r[4], r[5], r[6], r[7]);
    }
}

// ---------------- GAT layer 2 + log_softmax: single online pass ------------
__global__ void gat2_k(float* __restrict__ logp, const float* __restrict__ b2) {
    __shared__ float buf[8][C2];
    int lane = threadIdx.x & 31;
    int w = threadIdx.x >> 5;
    int n = blockIdx.x * (blockDim.x >> 5) + w;
    if (n >= NN) return;
    int h = lane >> 2, j = lane & 3;
    int base = g_off[n];
    int deg = g_off[n + 1] - base;
    float ald = g_al2d[n * NH + h];

    float m = -1e30f, s = 0.f;
    float acc[16];
#pragma unroll
    for (int o = 0; o < 16; o++) acc[o] = 0.f;

    for (int i = j; i < deg; i += 4) {
        int sr = g_srcs[base + i];
        float e = g_al2s[sr * NH + h] + ald;
        e = e > 0.f ? e : NEG_SLOPE * e;
        if (e > m) {
            float r = __expf(m - e);
            s *= r;
#pragma unroll
            for (int o = 0; o < 16; o++) acc[o] *= r;
            m = e;
        }
        float wgt = __expf(e - m);
        s += wgt;
        const float4* xr = (const float4*)&g_xw2[sr * C2 + h * 16];
#pragma unroll
        for (int q = 0; q < 4; q++) {
            float4 v = xr[q];
            acc[q * 4 + 0] += wgt * v.x;
            acc[q * 4 + 1] += wgt * v.y;
            acc[q * 4 + 2] += wgt * v.z;
            acc[q * 4 + 3] += wgt * v.w;
        }
    }
#pragma unroll
    for (int mask = 1; mask <= 2; mask <<= 1) {
        float mo = __shfl_xor_sync(0xffffffffu, m, mask);
        float so = __shfl_xor_sync(0xffffffffu, s, mask);
        float mm = fmaxf(m, mo);
        float cs = __expf(m - mm), co = __expf(mo - mm);
        s = s * cs + so * co;
#pragma unroll
        for (int o = 0; o < 16; o++) {
            float ao = __shfl_xor_sync(0xffffffffu, acc[o], mask);
            acc[o] = acc[o] * cs + ao * co;
        }
        m = mm;
    }
    if (j == 0) {
        float inv = 1.f / (s + 1e-16f);
#pragma unroll
        for (int o = 0; o < 16; o++)
            buf[w][h * 16 + o] = acc[o] * inv + b2[h * 16 + o];
    }
    __syncwarp();

    // log_softmax over the 128 logits of this node
    float v[4];
#pragma unroll
    for (int i = 0; i < 4; i++) v[i] = buf[w][lane * 4 + i];
    float mx = fmaxf(fmaxf(v[0], v[1]), fmaxf(v[2], v[3]));
#pragma unroll
    for (int off = 16; off >= 1; off >>= 1)
        mx = fmaxf(mx, __shfl_xor_sync(0xffffffffu, mx, off));
    float se = 0.f;
#pragma unroll
    for (int i = 0; i < 4; i++) se += __expf(v[i] - mx);
#pragma unroll
    for (int off = 16; off >= 1; off >>= 1)
        se += __shfl_xor_sync(0xffffffffu, se, off);
    float lse = mx + __logf(se);
    float4 o4 = make_float4(v[0] - lse, v[1] - lse, v[2] - lse, v[3] - lse);
    *(float4*)&logp[n * C2 + lane * 4] = o4;
}

// ---------------- launch ---------------------------------------------------
extern "C" void kernel_launch(void* const* d_in, const int* in_sizes, int n_in,
                              void* d_out, int out_size) {
    const float* x   = (const float*)d_in[0];
    const int*   ei  = (const int*)d_in[1];   // int32: JAX default (x64 disabled)
    const float* W1  = (const float*)d_in[2];
    const float* a1s = (const float*)d_in[3];
    const float* a1d = (const float*)d_in[4];
    const float* b1  = (const float*)d_in[5];
    const float* W2  = (const float*)d_in[6];
    const float* a2s = (const float*)d_in[7];
    const float* a2d = (const float*)d_in[8];
    const float* b2  = (const float*)d_in[9];

    float* out   = (float*)d_out;
    float* logp  = out;                // [NN, 128]
    float* alpha = out + NN * C2;      // [ET, 8]
    int alpha_rows = (out_size - NN * C2) / NH;
    if (alpha_rows < 0) alpha_rows = 0;

    // side stream + events, created once (outside capture: the correctness
    // call precedes graph capture). Non-blocking to avoid legacy-stream
    // implicit sync, which is illegal during capture.
    static cudaStream_t s_side = nullptr;
    static cudaEvent_t  ev_fork = nullptr, ev_join = nullptr;
    if (s_side == nullptr) {
        cudaStreamCreateWithFlags(&s_side, cudaStreamNonBlocking);
        cudaEventCreateWithFlags(&ev_fork, cudaEventDisableTiming);
        cudaEventCreateWithFlags(&ev_join, cudaEventDisableTiming);
    }

    // fork: CSR build on side stream, concurrent with gemm1 + al1
    cudaEventRecord(ev_fork, 0);
    cudaStreamWaitEvent(s_side, ev_fork, 0);

    init_deg_k<<<(NN / 4 + 256) / 256, 256, 0, s_side>>>();
    deg_k<<<(EIN / 4 + 255) / 256, 256, 0, s_side>>>(ei);
    scan_k<<<1, 1024, 0, s_side>>>();
    {
        const int nthr = EIN / 4 + (NN + 3) / 4;   // 212500
        scatter_k<<<(nthr + 255) / 256, 256, 0, s_side>>>(ei);
    }
    cudaEventRecord(ev_join, s_side);

    gemm1_k<<<(NN + 127) / 128, 256>>>(x, W1);
    al1_k<<<(NN * NH + 255) / 256, 256>>>(a1s, a1d);

    // join
    cudaStreamWaitEvent(0, ev_join, 0);

    gat1_k<<<(NN + 7) / 8, 256>>>(alpha, b1, alpha_rows);

    gemm2_k<<<(NN + 127) / 128, 256>>>(W2);
    al2_k<<<(NN * NH + 255) / 256, 256>>>(a2s, a2d);
    gat2_k<<<(NN + 7) / 8, 256>>>(logp, b2);
}

// round 6
// speedup vs baseline: 1.3927x; 1.0791x over previous
#include <cuda_runtime.h>
#include <cuda_bf16.h>
#include <cstdint>

#define NN  50000
#define EIN 800000
#define ET  850000   // EIN + NN self loops
#define FIN 256
#define C1  64       // H1*D1
#define C2  128      // H2*C
#define NH  8
#define NEG_SLOPE 0.2f

// ---------------- scratch (device globals; no allocation allowed) ----------
__device__ __align__(16) float g_xw1[NN * C1];
__device__ __align__(16) float g_al1s[NN * NH];
__device__ __align__(16) float g_al1d[NN * NH];
__device__ __align__(16) float g_h1[NN * C1];
__device__ __align__(16) float g_xw2[NN * C2];
__device__ __align__(16) float g_al2s[NN * NH];
__device__ __align__(16) float g_al2d[NN * NH];
__device__ __align__(16) int   g_deg[NN];
__device__ int   g_off[NN + 1];
__device__ int   g_cur[NN];
__device__ int   g_srcs[ET];
__device__ int   g_eid[ET];

// ---------------- helpers --------------------------------------------------
__device__ __forceinline__ uint32_t pkbf(float a, float b) {
    __nv_bfloat162 t = __floats2bfloat162_rn(a, b);   // .x = a (low 16 bits)
    return *(uint32_t*)&t;
}
__device__ __forceinline__ void mma_bf16(float* d, uint32_t a0, uint32_t a1,
                                         uint32_t a2, uint32_t a3,
                                         uint32_t b0, uint32_t b1) {
    asm volatile(
        "mma.sync.aligned.m16n8k16.row.col.f32.bf16.bf16.f32 "
        "{%0,%1,%2,%3}, {%4,%5,%6,%7}, {%8,%9}, {%0,%1,%2,%3};"
        : "+f"(d[0]), "+f"(d[1]), "+f"(d[2]), "+f"(d[3])
        : "r"(a0), "r"(a1), "r"(a2), "r"(a3), "r"(b0), "r"(b1));
}

// ---------------- CSR build ------------------------------------------------
__global__ void init_deg_k() {
    int n4 = blockIdx.x * blockDim.x + threadIdx.x;
    if (n4 * 4 + 3 < NN) {
        *(int4*)&g_deg[n4 * 4] = make_int4(1, 1, 1, 1);
    } else {
        for (int n = n4 * 4; n < NN; n++) g_deg[n] = 1;
    }
}

__global__ void deg_k(const int* __restrict__ ei) {
    int e4 = blockIdx.x * blockDim.x + threadIdx.x;
    if (e4 * 4 >= EIN) return;
    int4 d = *(const int4*)&ei[EIN + e4 * 4];
    atomicAdd(&g_deg[d.x], 1);
    atomicAdd(&g_deg[d.y], 1);
    atomicAdd(&g_deg[d.z], 1);
    atomicAdd(&g_deg[d.w], 1);
}

__global__ void scan_k() {
    __shared__ int part[1024];
    const int CH = (NN + 1023) / 1024;
    int t = threadIdx.x;
    int start = t * CH;
    int end = start + CH; if (end > NN) end = NN;
    if (start > NN) start = NN;
    int s = 0;
    for (int i = start; i < end; i++) s += g_deg[i];
    part[t] = s;
    __syncthreads();
    for (int off = 1; off < 1024; off <<= 1) {
        int v = 0;
        if (t >= off) v = part[t - off];
        __syncthreads();
        part[t] += v;
        __syncthreads();
    }
    int run = part[t] - s;
    for (int i = start; i < end; i++) {
        g_off[i] = run;
        g_cur[i] = run;
        run += g_deg[i];
    }
    if (end >= NN && start <= NN) g_off[NN] = run;
}

__global__ void scatter_k(const int* __restrict__ ei) {
    const int NE4 = EIN / 4;
    int t = blockIdx.x * blockDim.x + threadIdx.x;
    if (t < NE4) {
        int e = t * 4;
        int4 s = *(const int4*)&ei[e];
        int4 d = *(const int4*)&ei[EIN + e];
        int p;
        p = atomicAdd(&g_cur[d.x], 1); g_srcs[p] = s.x; g_eid[p] = e;
        p = atomicAdd(&g_cur[d.y], 1); g_srcs[p] = s.y; g_eid[p] = e + 1;
        p = atomicAdd(&g_cur[d.z], 1); g_srcs[p] = s.z; g_eid[p] = e + 2;
        p = atomicAdd(&g_cur[d.w], 1); g_srcs[p] = s.w; g_eid[p] = e + 3;
    } else {
        int n0 = (t - NE4) * 4;
        for (int k = 0; k < 4; k++) {
            int n = n0 + k;
            if (n < NN) {
                int p = atomicAdd(&g_cur[n], 1);
                g_srcs[p] = n; g_eid[p] = EIN + n;
            }
        }
    }
}

// ============ GEMM1 (mma.sync bf16x3): xw1 = x @ W1, fused al1 =============
// 128x64 tile, K=256 in 4 chunks of 64. 8 warps: warp w -> rows w*16..+15.
// SMEM rows at 144B stride -> conflict-free fragment LDS (bank = g*4+c).
#define S1ROW 144
#define G1_WS  0
#define G1_AHI 512
#define G1_ALO (G1_AHI + 128 * S1ROW)
#define G1_BHI (G1_ALO + 128 * S1ROW)
#define G1_BLO (G1_BHI + 64 * S1ROW)
#define G1_SMEM (G1_BLO + 64 * S1ROW)

__global__ __launch_bounds__(256) void gemm1_m(
    const float* __restrict__ A, const float* __restrict__ W,
    const float* __restrict__ a1s, const float* __restrict__ a1d) {
    extern __shared__ char sm[];
    float* ws = (float*)(sm + G1_WS);
    int tid = threadIdx.x, wid = tid >> 5, lid = tid & 31;
    int g = lid >> 2, c = lid & 3;
    int row0 = blockIdx.x * 128;

    if (tid < 64) ws[tid] = a1s[tid];
    else if (tid < 128) ws[tid] = a1d[tid - 64];

    float d[8][4];
#pragma unroll
    for (int nt = 0; nt < 8; nt++)
#pragma unroll
        for (int q = 0; q < 4; q++) d[nt][q] = 0.f;

    for (int kc = 0; kc < 4; kc++) {
        if (kc) __syncthreads();
        // stage A: 128 rows x 64 k (fp32 -> bf16 hi/lo)
#pragma unroll
        for (int it = 0; it < 8; it++) {
            int idx = tid + it * 256;
            int r = idx >> 4, k = (idx & 15) << 2;
            int gr = row0 + r;
            float4 v = (gr < NN) ? *(const float4*)&A[(size_t)gr * FIN + kc * 64 + k]
                                 : make_float4(0.f, 0.f, 0.f, 0.f);
            uint32_t h0 = pkbf(v.x, v.y), h1 = pkbf(v.z, v.w);
            float rx = v.x - __bfloat162float(__float2bfloat16(v.x));
            float ry = v.y - __bfloat162float(__float2bfloat16(v.y));
            float rz = v.z - __bfloat162float(__float2bfloat16(v.z));
            float rw = v.w - __bfloat162float(__float2bfloat16(v.w));
            uint32_t l0 = pkbf(rx, ry), l1 = pkbf(rz, rw);
            *(uint2*)(sm + G1_AHI + r * S1ROW + k * 2) = make_uint2(h0, h1);
            *(uint2*)(sm + G1_ALO + r * S1ROW + k * 2) = make_uint2(l0, l1);
        }
        // stage B: B[n][k] = W[kc*64+k][n], 64 x 64
#pragma unroll
        for (int it = 0; it < 4; it++) {
            int idx = tid + it * 256;
            int n = idx & 63, k = (idx >> 6) << 2;
            float v0 = W[(kc * 64 + k) * 64 + n];
            float v1 = W[(kc * 64 + k + 1) * 64 + n];
            float v2 = W[(kc * 64 + k + 2) * 64 + n];
            float v3 = W[(kc * 64 + k + 3) * 64 + n];
            uint32_t h0 = pkbf(v0, v1), h1 = pkbf(v2, v3);
            uint32_t l0 = pkbf(v0 - __bfloat162float(__float2bfloat16(v0)),
                               v1 - __bfloat162float(__float2bfloat16(v1)));
            uint32_t l1 = pkbf(v2 - __bfloat162float(__float2bfloat16(v2)),
                               v3 - __bfloat162float(__float2bfloat16(v3)));
            *(uint2*)(sm + G1_BHI + n * S1ROW + k * 2) = make_uint2(h0, h1);
            *(uint2*)(sm + G1_BLO + n * S1ROW + k * 2) = make_uint2(l0, l1);
        }
        __syncthreads();

#pragma unroll
        for (int ks = 0; ks < 4; ks++) {
            int k0 = ks * 16;
            const char* pah = sm + G1_AHI + (wid * 16 + g) * S1ROW + (k0 + c * 2) * 2;
            const char* pal = sm + G1_ALO + (wid * 16 + g) * S1ROW + (k0 + c * 2) * 2;
            uint32_t ah0 = *(const uint32_t*)(pah);
            uint32_t ah1 = *(const uint32_t*)(pah + 8 * S1ROW);
            uint32_t ah2 = *(const uint32_t*)(pah + 16);
            uint32_t ah3 = *(const uint32_t*)(pah + 8 * S1ROW + 16);
            uint32_t al0 = *(const uint32_t*)(pal);
            uint32_t al1 = *(const uint32_t*)(pal + 8 * S1ROW);
            uint32_t al2 = *(const uint32_t*)(pal + 16);
            uint32_t al3 = *(const uint32_t*)(pal + 8 * S1ROW + 16);
#pragma unroll
            for (int nt = 0; nt < 8; nt++) {
                const char* pbh = sm + G1_BHI + (nt * 8 + g) * S1ROW + (k0 + c * 2) * 2;
                const char* pbl = sm + G1_BLO + (nt * 8 + g) * S1ROW + (k0 + c * 2) * 2;
                uint32_t bh0 = *(const uint32_t*)(pbh);
                uint32_t bh1 = *(const uint32_t*)(pbh + 16);
                uint32_t bl0 = *(const uint32_t*)(pbl);
                uint32_t bl1 = *(const uint32_t*)(pbl + 16);
                mma_bf16(d[nt], ah0, ah1, ah2, ah3, bh0, bh1);
                mma_bf16(d[nt], ah0, ah1, ah2, ah3, bl0, bl1);
                mma_bf16(d[nt], al0, al1, al2, al3, bh0, bh1);
            }
        }
    }

    // epilogue: rows r1 = row0 + wid*16 + g, r2 = r1 + 8; cols nt*8 + c*2
    int r1 = row0 + wid * 16 + g, r2 = r1 + 8;
#pragma unroll
    for (int nt = 0; nt < 8; nt++) {
        if (r1 < NN) *(float2*)&g_xw1[(size_t)r1 * C1 + nt * 8 + c * 2] = make_float2(d[nt][0], d[nt][1]);
        if (r2 < NN) *(float2*)&g_xw1[(size_t)r2 * C1 + nt * 8 + c * 2] = make_float2(d[nt][2], d[nt][3]);
    }
    // fused al1 dots (head h == nt)
#pragma unroll
    for (int h = 0; h < 8; h++) {
        int wcol = h * 8 + c * 2;
        float s1 = d[h][0] * ws[wcol] + d[h][1] * ws[wcol + 1];
        float t1 = d[h][0] * ws[64 + wcol] + d[h][1] * ws[64 + wcol + 1];
        float s2 = d[h][2] * ws[wcol] + d[h][3] * ws[wcol + 1];
        float t2 = d[h][2] * ws[64 + wcol] + d[h][3] * ws[64 + wcol + 1];
#pragma unroll
        for (int mk = 1; mk <= 2; mk <<= 1) {
            s1 += __shfl_xor_sync(0xffffffffu, s1, mk);
            t1 += __shfl_xor_sync(0xffffffffu, t1, mk);
            s2 += __shfl_xor_sync(0xffffffffu, s2, mk);
            t2 += __shfl_xor_sync(0xffffffffu, t2, mk);
        }
        if (c == 0) {
            if (r1 < NN) { g_al1s[r1 * NH + h] = s1; g_al1d[r1 * NH + h] = t1; }
            if (r2 < NN) { g_al1s[r2 * NH + h] = s2; g_al1d[r2 * NH + h] = t2; }
        }
    }
}

// ============ GEMM2 (mma.sync bf16x3): xw2 = h1 @ W2, fused al2 =============
// 128x128 tile, K=64 single chunk. 8 warps, 16 n-tiles per warp.
#define G2_WS  0
#define G2_AHI 1024
#define G2_ALO (G2_AHI + 128 * S1ROW)
#define G2_BHI (G2_ALO + 128 * S1ROW)
#define G2_BLO (G2_BHI + 128 * S1ROW)
#define G2_SMEM (G2_BLO + 128 * S1ROW)

__global__ __launch_bounds__(256) void gemm2_m(
    const float* __restrict__ W,
    const float* __restrict__ a2s, const float* __restrict__ a2d) {
    extern __shared__ char sm[];
    float* ws = (float*)(sm + G2_WS);
    int tid = threadIdx.x, wid = tid >> 5, lid = tid & 31;
    int g = lid >> 2, c = lid & 3;
    int row0 = blockIdx.x * 128;

    if (tid < 128) ws[tid] = a2s[tid];
    else ws[tid] = a2d[tid - 128];

    // stage A: g_h1 128 rows x 64 k
#pragma unroll
    for (int it = 0; it < 8; it++) {
        int idx = tid + it * 256;
        int r = idx >> 4, k = (idx & 15) << 2;
        int gr = row0 + r;
        float4 v = (gr < NN) ? *(const float4*)&g_h1[(size_t)gr * C1 + k]
                             : make_float4(0.f, 0.f, 0.f, 0.f);
        uint32_t h0 = pkbf(v.x, v.y), h1 = pkbf(v.z, v.w);
        uint32_t l0 = pkbf(v.x - __bfloat162float(__float2bfloat16(v.x)),
                           v.y - __bfloat162float(__float2bfloat16(v.y)));
        uint32_t l1 = pkbf(v.z - __bfloat162float(__float2bfloat16(v.z)),
                           v.w - __bfloat162float(__float2bfloat16(v.w)));
        *(uint2*)(sm + G2_AHI + r * S1ROW + k * 2) = make_uint2(h0, h1);
        *(uint2*)(sm + G2_ALO + r * S1ROW + k * 2) = make_uint2(l0, l1);
    }
    // stage B: B[n][k] = W2[k][n], 128 n x 64 k
#pragma unroll
    for (int it = 0; it < 8; it++) {
        int idx = tid + it * 256;
        int n = idx & 127, k = (idx >> 7) << 2;
        float v0 = W[(k) * 128 + n];
        float v1 = W[(k + 1) * 128 + n];
        float v2 = W[(k + 2) * 128 + n];
        float v3 = W[(k + 3) * 128 + n];
        uint32_t h0 = pkbf(v0, v1), h1 = pkbf(v2, v3);
        uint32_t l0 = pkbf(v0 - __bfloat162float(__float2bfloat16(v0)),
                           v1 - __bfloat162float(__float2bfloat16(v1)));
        uint32_t l1 = pkbf(v2 - __bfloat162float(__float2bfloat16(v2)),
                           v3 - __bfloat162float(__float2bfloat16(v3)));
        *(uint2*)(sm + G2_BHI + n * S1ROW + k * 2) = make_uint2(h0, h1);
        *(uint2*)(sm + G2_BLO + n * S1ROW + k * 2) = make_uint2(l0, l1);
    }
    __syncthreads();

    float d[16][4];
#pragma unroll
    for (int nt = 0; nt < 16; nt++)
#pragma unroll
        for (int q = 0; q < 4; q++) d[nt][q] = 0.f;

#pragma unroll
    for (int ks = 0; ks < 4; ks++) {
        int k0 = ks * 16;
        const char* pah = sm + G2_AHI + (wid * 16 + g) * S1ROW + (k0 + c * 2) * 2;
        const char* pal = sm + G2_ALO + (wid * 16 + g) * S1ROW + (k0 + c * 2) * 2;
        uint32_t ah0 = *(const uint32_t*)(pah);
        uint32_t ah1 = *(const uint32_t*)(pah + 8 * S1ROW);
        uint32_t ah2 = *(const uint32_t*)(pah + 16);
        uint32_t ah3 = *(const uint32_t*)(pah + 8 * S1ROW + 16);
        uint32_t al0 = *(const uint32_t*)(pal);
        uint32_t al1 = *(const uint32_t*)(pal + 8 * S1ROW);
        uint32_t al2 = *(const uint32_t*)(pal + 16);
        uint32_t al3 = *(const uint32_t*)(pal + 8 * S1ROW + 16);
#pragma unroll
        for (int nt = 0; nt < 16; nt++) {
            const char* pbh = sm + G2_BHI + (nt * 8 + g) * S1ROW + (k0 + c * 2) * 2;
            const char* pbl = sm + G2_BLO + (nt * 8 + g) * S1ROW + (k0 + c * 2) * 2;
            uint32_t bh0 = *(const uint32_t*)(pbh);
            uint32_t bh1 = *(const uint32_t*)(pbh + 16);
            uint32_t bl0 = *(const uint32_t*)(pbl);
            uint32_t bl1 = *(const uint32_t*)(pbl + 16);
            mma_bf16(d[nt], ah0, ah1, ah2, ah3, bh0, bh1);
            mma_bf16(d[nt], ah0, ah1, ah2, ah3, bl0, bl1);
            mma_bf16(d[nt], al0, al1, al2, al3, bh0, bh1);
        }
    }

    int r1 = row0 + wid * 16 + g, r2 = r1 + 8;
#pragma unroll
    for (int nt = 0; nt < 16; nt++) {
        if (r1 < NN) *(float2*)&g_xw2[(size_t)r1 * C2 + nt * 8 + c * 2] = make_float2(d[nt][0], d[nt][1]);
        if (r2 < NN) *(float2*)&g_xw2[(size_t)r2 * C2 + nt * 8 + c * 2] = make_float2(d[nt][2], d[nt][3]);
    }
    // fused al2 (head h spans n-tiles 2h, 2h+1)
#pragma unroll
    for (int h = 0; h < 8; h++) {
        float s1 = 0.f, t1 = 0.f, s2 = 0.f, t2 = 0.f;
#pragma unroll
        for (int sub = 0; sub < 2; sub++) {
            int nt = h * 2 + sub;
            int wcol = nt * 8 + c * 2;
            s1 += d[nt][0] * ws[wcol] + d[nt][1] * ws[wcol + 1];
            t1 += d[nt][0] * ws[128 + wcol] + d[nt][1] * ws[128 + wcol + 1];
            s2 += d[nt][2] * ws[wcol] + d[nt][3] * ws[wcol + 1];
            t2 += d[nt][2] * ws[128 + wcol] + d[nt][3] * ws[128 + wcol + 1];
        }
#pragma unroll
        for (int mk = 1; mk <= 2; mk <<= 1) {
            s1 += __shfl_xor_sync(0xffffffffu, s1, mk);
            t1 += __shfl_xor_sync(0xffffffffu, t1, mk);
            s2 += __shfl_xor_sync(0xffffffffu, s2, mk);
            t2 += __shfl_xor_sync(0xffffffffu, t2, mk);
        }
        if (c == 0) {
            if (r1 < NN) { g_al2s[r1 * NH + h] = s1; g_al2d[r1 * NH + h] = t1; }
            if (r2 < NN) { g_al2s[r2 * NH + h] = s2; g_al2d[r2 * NH + h] = t2; }
        }
    }
}

// ---------------- GAT layer 1: one warp per dst node, 2 passes -------------
__global__ void gat1_k(float* __restrict__ alpha_out, const float* __restrict__ b1,
                       int alpha_rows) {
    int lane = threadIdx.x & 31;
    int n = blockIdx.x * (blockDim.x >> 5) + (threadIdx.x >> 5);
    if (n >= NN) return;
    int h = lane >> 2, j = lane & 3;
    int base = g_off[n];
    int deg = g_off[n + 1] - base;
    float ald = g_al1d[n * NH + h];

    float m = -1e30f, s = 0.f;
    for (int i = j; i < deg; i += 4) {
        int sr = g_srcs[base + i];
        float e = g_al1s[sr * NH + h] + ald;
        e = e > 0.f ? e : NEG_SLOPE * e;
        if (e > m) { s *= __expf(m - e); m = e; }
        s += __expf(e - m);
    }
#pragma unroll
    for (int mask = 1; mask <= 2; mask <<= 1) {
        float mo = __shfl_xor_sync(0xffffffffu, m, mask);
        float so = __shfl_xor_sync(0xffffffffu, s, mask);
        float mm = fmaxf(m, mo);
        s = s * __expf(m - mm) + so * __expf(mo - mm);
        m = mm;
    }
    float inv = 1.f / (s + 1e-16f);

    float acc[8];
#pragma unroll
    for (int o = 0; o < 8; o++) acc[o] = 0.f;
    for (int i = j; i < deg; i += 4) {
        int sr = g_srcs[base + i];
        float e = g_al1s[sr * NH + h] + ald;
        e = e > 0.f ? e : NEG_SLOPE * e;
        float w = __expf(e - m) * inv;
        int eid = g_eid[base + i];
        if (eid < alpha_rows)
            alpha_out[eid * NH + h] = w;
        const float4* xr = (const float4*)&g_xw1[sr * C1 + h * 8];
        float4 v0 = xr[0], v1 = xr[1];
        acc[0] += w * v0.x; acc[1] += w * v0.y; acc[2] += w * v0.z; acc[3] += w * v0.w;
        acc[4] += w * v1.x; acc[5] += w * v1.y; acc[6] += w * v1.z; acc[7] += w * v1.w;
    }
#pragma unroll
    for (int o = 0; o < 8; o++) {
        acc[o] += __shfl_xor_sync(0xffffffffu, acc[o], 1);
        acc[o] += __shfl_xor_sync(0xffffffffu, acc[o], 2);
    }
    if (j == 0) {
        float r[8];
#pragma unroll
        for (int o = 0; o < 8; o++) {
            float v = acc[o] + b1[h * 8 + o];
            r[o] = v > 0.f ? v : (__expf(v) - 1.f);   // ELU
        }
        float4* dst = (float4*)&g_h1[n * C1 + h * 8];
        dst[0] = make_float4(r[0], r[1], r[2], r[3]);
        dst[1] = make_float4(r[4], r[5], r[6], r[7]);
    }
}

// ---------------- GAT layer 2 + log_softmax: single online pass ------------
__global__ void gat2_k(float* __restrict__ logp, const float* __restrict__ b2) {
    __shared__ float buf[8][C2];
    int lane = threadIdx.x & 31;
    int w = threadIdx.x >> 5;
    int n = blockIdx.x * (blockDim.x >> 5) + w;
    if (n >= NN) return;
    int h = lane >> 2, j = lane & 3;
    int base = g_off[n];
    int deg = g_off[n + 1] - base;
    float ald = g_al2d[n * NH + h];

    float m = -1e30f, s = 0.f;
    float acc[16];
#pragma unroll
    for (int o = 0; o < 16; o++) acc[o] = 0.f;

    for (int i = j; i < deg; i += 4) {
        int sr = g_srcs[base + i];
        float e = g_al2s[sr * NH + h] + ald;
        e = e > 0.f ? e : NEG_SLOPE * e;
        if (e > m) {
            float r = __expf(m - e);
            s *= r;
#pragma unroll
            for (int o = 0; o < 16; o++) acc[o] *= r;
            m = e;
        }
        float wgt = __expf(e - m);
        s += wgt;
        const float4* xr = (const float4*)&g_xw2[sr * C2 + h * 16];
#pragma unroll
        for (int q = 0; q < 4; q++) {
            float4 v = xr[q];
            acc[q * 4 + 0] += wgt * v.x;
            acc[q * 4 + 1] += wgt * v.y;
            acc[q * 4 + 2] += wgt * v.z;
            acc[q * 4 + 3] += wgt * v.w;
        }
    }
#pragma unroll
    for (int mask = 1; mask <= 2; mask <<= 1) {
        float mo = __shfl_xor_sync(0xffffffffu, m, mask);
        float so = __shfl_xor_sync(0xffffffffu, s, mask);
        float mm = fmaxf(m, mo);
        float cs = __expf(m - mm), co = __expf(mo - mm);
        s = s * cs + so * co;
#pragma unroll
        for (int o = 0; o < 16; o++) {
            float ao = __shfl_xor_sync(0xffffffffu, acc[o], mask);
            acc[o] = acc[o] * cs + ao * co;
        }
        m = mm;
    }
    if (j == 0) {
        float inv = 1.f / (s + 1e-16f);
#pragma unroll
        for (int o = 0; o < 16; o++)
            buf[w][h * 16 + o] = acc[o] * inv + b2[h * 16 + o];
    }
    __syncwarp();

    float v[4];
#pragma unroll
    for (int i = 0; i < 4; i++) v[i] = buf[w][lane * 4 + i];
    float mx = fmaxf(fmaxf(v[0], v[1]), fmaxf(v[2], v[3]));
#pragma unroll
    for (int off = 16; off >= 1; off >>= 1)
        mx = fmaxf(mx, __shfl_xor_sync(0xffffffffu, mx, off));
    float se = 0.f;
#pragma unroll
    for (int i = 0; i < 4; i++) se += __expf(v[i] - mx);
#pragma unroll
    for (int off = 16; off >= 1; off >>= 1)
        se += __shfl_xor_sync(0xffffffffu, se, off);
    float lse = mx + __logf(se);
    float4 o4 = make_float4(v[0] - lse, v[1] - lse, v[2] - lse, v[3] - lse);
    *(float4*)&logp[n * C2 + lane * 4] = o4;
}

// ---------------- launch ---------------------------------------------------
extern "C" void kernel_launch(void* const* d_in, const int* in_sizes, int n_in,
                              void* d_out, int out_size) {
    const float* x   = (const float*)d_in[0];
    const int*   ei  = (const int*)d_in[1];
    const float* W1  = (const float*)d_in[2];
    const float* a1s = (const float*)d_in[3];
    const float* a1d = (const float*)d_in[4];
    const float* b1  = (const float*)d_in[5];
    const float* W2  = (const float*)d_in[6];
    const float* a2s = (const float*)d_in[7];
    const float* a2d = (const float*)d_in[8];
    const float* b2  = (const float*)d_in[9];

    float* out   = (float*)d_out;
    float* logp  = out;                // [NN, 128]
    float* alpha = out + NN * C2;      // [ET, 8]
    int alpha_rows = (out_size - NN * C2) / NH;
    if (alpha_rows < 0) alpha_rows = 0;

    static cudaStream_t s_side = nullptr;
    static cudaEvent_t  ev_fork = nullptr, ev_join = nullptr;
    if (s_side == nullptr) {
        cudaStreamCreateWithFlags(&s_side, cudaStreamNonBlocking);
        cudaEventCreateWithFlags(&ev_fork, cudaEventDisableTiming);
        cudaEventCreateWithFlags(&ev_join, cudaEventDisableTiming);
        cudaFuncSetAttribute(gemm1_m, cudaFuncAttributeMaxDynamicSharedMemorySize, G1_SMEM);
        cudaFuncSetAttribute(gemm2_m, cudaFuncAttributeMaxDynamicSharedMemorySize, G2_SMEM);
    }

    // fork: CSR build on side stream, concurrent with gemm1
    cudaEventRecord(ev_fork, 0);
    cudaStreamWaitEvent(s_side, ev_fork, 0);

    init_deg_k<<<(NN / 4 + 256) / 256, 256, 0, s_side>>>();
    deg_k<<<(EIN / 4 + 255) / 256, 256, 0, s_side>>>(ei);
    scan_k<<<1, 1024, 0, s_side>>>();
    {
        const int nthr = EIN / 4 + (NN + 3) / 4;
        scatter_k<<<(nthr + 255) / 256, 256, 0, s_side>>>(ei);
    }
    cudaEventRecord(ev_join, s_side);

    gemm1_m<<<(NN + 127) / 128, 256, G1_SMEM>>>(x, W1, a1s, a1d);

    cudaStreamWaitEvent(0, ev_join, 0);

    gat1_k<<<(NN + 7) / 8, 256>>>(alpha, b1, alpha_rows);
    gemm2_m<<<(NN + 127) / 128, 256, G2_SMEM>>>(W2, a2s, a2d);
    gat2_k<<<(NN + 7) / 8, 256>>>(logp, b2);
}